// round 3
// baseline (speedup 1.0000x reference)
#include <cuda_runtime.h>
#include <cuda_bf16.h>

// FGPillarMaxPooling: per-point pillar assignment -> 7->32 linear + ReLU ->
// scatter-max into dense BEV grid (B, 512, 512, 32).
//
// Strategy:
//  - cudaMemsetAsync(d_out, 0): relu outputs are >= 0 and empty pillars must
//    be 0 (segment_max -inf replaced by 0), so zero is the correct identity.
//  - int atomicMax with __float_as_int: valid because all candidates are
//    non-negative floats (bit pattern order == float order on [0, +inf)).
//  - skip the atomic entirely when acc == 0 (relu kills ~half the lanes;
//    buffer already holds 0) -> halves REDG traffic.

#define PCR_X0 (-51.2f)
#define PCR_Y0 (-51.2f)
#define PS     (0.2f)
#define GW     512
#define GH     512
#define COUT   32
#define NFEAT  7   // CIN(4) + 3 geometric offsets

__global__ void fg_pillar_maxpool_kernel(const float* __restrict__ xyz,
                                         const int*   __restrict__ batch_cnt, int B,
                                         const float* __restrict__ pt_feature,
                                         const float* __restrict__ W,   // (7, 32) row-major
                                         float*       __restrict__ out, // (B*GH*GW, 32)
                                         int N)
{
    __shared__ float sW[NFEAT * COUT];
    for (int t = threadIdx.x; t < NFEAT * COUT; t += blockDim.x)
        sW[t] = W[t];
    __syncthreads();

    const float4* __restrict__ feat4 = (const float4*)pt_feature;

    for (int i = blockIdx.x * blockDim.x + threadIdx.x; i < N;
         i += gridDim.x * blockDim.x) {

        // ---- point coords ----
        const float x = xyz[3 * i + 0];
        const float y = xyz[3 * i + 1];
        const float z = xyz[3 * i + 2];

        // ---- pillar cell (match JAX: floor((x - x0)/PS), precise division) ----
        int px = (int)floorf((x - PCR_X0) / PS);
        int py = (int)floorf((y - PCR_Y0) / PS);
        px = min(max(px, 0), GW - 1);
        py = min(max(py, 0), GH - 1);

        // ---- pillar center, relative offsets ----
        const float cx = ((float)px + 0.5f) * PS + PCR_X0;
        const float cy = ((float)py + 0.5f) * PS + PCR_Y0;
        const float cz = -1.0f;   // 0.5*(-5.0 + 3.0)

        // ---- gathered features: [pt_feature(4), dx, dy, dz] ----
        const float4 pf = feat4[i];
        float f[NFEAT];
        f[0] = pf.x; f[1] = pf.y; f[2] = pf.z; f[3] = pf.w;
        f[4] = x - cx;
        f[5] = y - cy;
        f[6] = z - cz;

        // ---- batch index from counts (B is tiny; cached reads) ----
        int b = 0;
        int cum = batch_cnt[0];
        while (b < B - 1 && i >= cum) { ++b; cum += batch_cnt[b]; }

        const int seg = b * (GH * GW) + py * GW + px;
        int* o = (int*)(out + (size_t)seg * COUT);   // one 128B line per pillar

        // ---- 7x32 linear + relu + predicated scatter-max ----
        #pragma unroll
        for (int c = 0; c < COUT; c++) {
            float acc = 0.0f;
            #pragma unroll
            for (int k = 0; k < NFEAT; k++)
                acc = fmaf(f[k], sW[k * COUT + c], acc);
            if (acc > 0.0f)                       // relu + skip-no-op-atomic
                atomicMax(o + c, __float_as_int(acc));
        }
    }
}

extern "C" void kernel_launch(void* const* d_in, const int* in_sizes, int n_in,
                              void* d_out, int out_size)
{
    const float* xyz  = (const float*)d_in[0];   // (N,3)
    const int*   cnt  = (const int*)  d_in[1];   // (B,)
    const float* feat = (const float*)d_in[2];   // (N,4)
    const float* W    = (const float*)d_in[3];   // (7,32)
    float* out        = (float*)d_out;

    const int N = in_sizes[0] / 3;
    const int B = in_sizes[1];

    // Zero-init: correct identity for relu-valued segment max; also covers
    // empty pillars (reference maps -inf -> 0).
    cudaMemsetAsync(d_out, 0, (size_t)out_size * sizeof(float), 0);

    const int threads = 256;
    const int blocks  = (N + threads - 1) / threads;
    fg_pillar_maxpool_kernel<<<blocks, threads>>>(xyz, cnt, B, feat, W, out, N);
}

// round 6
// speedup vs baseline: 2.0456x; 2.0456x over previous
#include <cuda_runtime.h>
#include <cuda_bf16.h>

// FGPillarMaxPooling — round 4 (resubmit of round-3 design; prior run was an
// infra flake, never measured).
//
// Phase A (1 thread = 1 point): pillar cell, geometric offsets, batch index;
//   stash [f0..f6, seg] in shared memory as two float4s.
// Phase B (1 warp x 32 points, lane = output channel): lane c keeps W[:,c] in
//   registers; per point: 2 broadcast LDS.128 + 7 FMA + 1 predicated
//   atomicMax into ONE 128B line (coalesced -> <=4 L2 sector RMWs/point,
//   vs 32 scattered in the round-2 layout that ran at L2=59%).
//
// Zero-init memset is the exact max-identity (relu >= 0, empty pillars -> 0);
// int atomicMax == float max for non-negative floats.

#define PCR_X0 (-51.2f)
#define PCR_Y0 (-51.2f)
#define PS     (0.2f)
#define GW     512
#define GH     512
#define COUT   32
#define TPB    256          // threads per block = points per tile

__global__ __launch_bounds__(TPB)
void fg_pillar_maxpool_kernel(const float* __restrict__ xyz,
                              const int*   __restrict__ batch_cnt, int B,
                              const float* __restrict__ pt_feature,
                              const float* __restrict__ W,   // (7, 32) row-major
                              float*       __restrict__ out, // (B*GH*GW, 32)
                              int N)
{
    __shared__ float4 sA[TPB];   // f0..f3
    __shared__ float4 sB[TPB];   // f4, f5, f6, seg(bits)

    const int tid  = threadIdx.x;
    const int lane = tid & 31;
    const int warp = tid >> 5;

    // ---- per-lane weight column: W[k][lane], k = 0..6 (coalesced, L1-resident) ----
    const float w0 = __ldg(W + 0 * COUT + lane);
    const float w1 = __ldg(W + 1 * COUT + lane);
    const float w2 = __ldg(W + 2 * COUT + lane);
    const float w3 = __ldg(W + 3 * COUT + lane);
    const float w4 = __ldg(W + 4 * COUT + lane);
    const float w5 = __ldg(W + 5 * COUT + lane);
    const float w6 = __ldg(W + 6 * COUT + lane);

    // ================= Phase A: per-point setup =================
    const int p = blockIdx.x * TPB + tid;
    if (p < N) {
        const float x = xyz[3 * p + 0];
        const float y = xyz[3 * p + 1];
        const float z = xyz[3 * p + 2];

        int px = (int)floorf((x - PCR_X0) / PS);
        int py = (int)floorf((y - PCR_Y0) / PS);
        px = min(max(px, 0), GW - 1);
        py = min(max(py, 0), GH - 1);

        const float cx = ((float)px + 0.5f) * PS + PCR_X0;
        const float cy = ((float)py + 0.5f) * PS + PCR_Y0;
        const float cz = -1.0f;   // 0.5 * (-5.0 + 3.0)

        const float4 pf = ((const float4*)pt_feature)[p];

        // branchless batch index from prefix counts (B small; L1-resident)
        int b = 0, cum = 0;
        #pragma unroll 4
        for (int k = 0; k < B - 1; k++) {
            cum += batch_cnt[k];
            b += (p >= cum) ? 1 : 0;
        }

        const int seg = b * (GH * GW) + py * GW + px;

        sA[tid] = make_float4(pf.x, pf.y, pf.z, pf.w);
        sB[tid] = make_float4(x - cx, y - cy, z - cz, __int_as_float(seg));
    } else {
        sA[tid] = make_float4(0.f, 0.f, 0.f, 0.f);
        sB[tid] = make_float4(0.f, 0.f, 0.f, __int_as_float(-1));
    }
    __syncthreads();

    // ========= Phase B: channel-per-lane MLP + coalesced scatter-max =========
    int* __restrict__ iout = (int*)out;
    const int base = warp * 32;

    #pragma unroll 8
    for (int j = 0; j < 32; j++) {
        const float4 a = sA[base + j];   // broadcast LDS.128
        const float4 g = sB[base + j];   // broadcast LDS.128
        const int seg  = __float_as_int(g.w);
        if (seg < 0) continue;

        float acc;
        acc = fmaf(a.x, w0,
              fmaf(a.y, w1,
              fmaf(a.z, w2,
              fmaf(a.w, w3,
              fmaf(g.x, w4,
              fmaf(g.y, w5,
                   g.z * w6))))));

        if (acc > 0.0f)   // relu + skip-no-op atomic (buffer already 0)
            atomicMax(iout + seg * COUT + lane, __float_as_int(acc));
    }
}

extern "C" void kernel_launch(void* const* d_in, const int* in_sizes, int n_in,
                              void* d_out, int out_size)
{
    const float* xyz  = (const float*)d_in[0];   // (N,3)
    const int*   cnt  = (const int*)  d_in[1];   // (B,)
    const float* feat = (const float*)d_in[2];   // (N,4)
    const float* W    = (const float*)d_in[3];   // (7,32)
    float* out        = (float*)d_out;

    const int N = in_sizes[0] / 3;
    const int B = in_sizes[1];

    cudaMemsetAsync(d_out, 0, (size_t)out_size * sizeof(float), 0);

    const int blocks = (N + TPB - 1) / TPB;
    fg_pillar_maxpool_kernel<<<blocks, TPB>>>(xyz, cnt, B, feat, W, out, N);
}